// round 1
// baseline (speedup 1.0000x reference)
#include <cuda_runtime.h>
#include <cuda_bf16.h>

// ---------------- problem dims ----------------
#define NOBS   72000
#define NB     9000
#define LMAX   8
#define DIM    256
#define NTOK   8
#define HEADS  8
#define DHEAD  32
#define DEPTH  8
#define FF     1024
#define OUTD   2048
#define CL     512

// ---------------- scratch (device globals; allocation-free) ----------------
__device__ float g_bufA[NOBS * DIM];   // 73.7 MB
__device__ float g_bufB[NOBS * DIM];
__device__ float g_ctx [NOBS * DIM];   // bucket-major: row = b*8 + slot
__device__ float g_K   [NOBS * DIM];
__device__ float g_V   [NOBS * DIM];
__device__ float g_trx [NOBS * DIM];   // tr_x flattened: row = b*8 + tok
__device__ float g_ff  [NOBS * FF];    // 295 MB FFN mid
__device__ int   g_dest[NOBS];
__device__ int   g_cnt [NB];

// ---------------- helpers ----------------
__device__ __forceinline__ float gelu_tanh(float x) {
    const float k0 = 0.7978845608028654f;   // sqrt(2/pi)
    const float k1 = 0.044715f;
    return 0.5f * x * (1.0f + tanhf(k0 * (x + k1 * x * x * x)));
}

// ---------------- bucket slot assignment ----------------
__global__ void zero_cnt_kernel(int* cnt) {
    int i = blockIdx.x * 256 + threadIdx.x;
    if (i < NB) cnt[i] = 0;
}

__global__ void dest_kernel(const int* __restrict__ li, int* __restrict__ cnt,
                            int* __restrict__ dest) {
    int i = blockIdx.x * 256 + threadIdx.x;
    if (i >= NOBS) return;
    int f = li[3*i] * 1800 + li[3*i+1] * 60 + li[3*i+2];
    int slot = atomicAdd(&cnt[f], 1);
    dest[i] = f * LMAX + slot;
}

// ---------------- init tr_x with broadcast bg tokens ----------------
__global__ void init_trx_kernel(const float* __restrict__ bg, float* __restrict__ trx) {
    // grid: NOBS blocks of 256 threads; row = blockIdx.x, col = threadIdx.x
    int tok = blockIdx.x & 7;
    trx[(long)blockIdx.x * DIM + threadIdx.x] = bg[tok * DIM + threadIdx.x];
}

// ---------------- generic tiled GEMM: C = epi(A[M,K] @ B[K,N] + bias) ----------------
// GELU: apply tanh-gelu; RES: C += C (residual read from output buffer);
// rowmap: optional output-row scatter (used to dispatch MLP output into ctx).
#define BM 64
#define BN 64
#define BKT 16

template<bool GELU, bool RES>
__global__ __launch_bounds__(256)
void gemm_kernel(const float* __restrict__ A, const float* __restrict__ B,
                 const float* __restrict__ bias, float* __restrict__ C,
                 const int* __restrict__ rowmap, int M, int N, int K) {
    __shared__ float As[BKT][BM];
    __shared__ float Bs[BKT][BN];

    const int tid = threadIdx.x;
    const int m0 = blockIdx.y * BM;
    const int n0 = blockIdx.x * BN;

    const int tx = tid & 15;          // 16 cols of threads
    const int ty = tid >> 4;          // 16 rows of threads

    // A tile loader: 64 rows x 16 k; one float4 per thread
    const int ar = tid >> 2;          // 0..63
    const int ak = (tid & 3) * 4;     // 0,4,8,12
    // B tile loader: 16 rows x 64 n; one float4 per thread
    const int br = tid >> 4;          // 0..15
    const int bc = (tid & 15) * 4;    // 0..60

    const float* Aptr = A + (long)(m0 + ar) * K + ak;
    const float* Bptr = B + (long)br * N + n0 + bc;
    const bool arow_ok = (m0 + ar) < M;

    float acc[4][4];
#pragma unroll
    for (int i = 0; i < 4; i++)
#pragma unroll
        for (int j = 0; j < 4; j++) acc[i][j] = 0.0f;

    for (int k0 = 0; k0 < K; k0 += BKT) {
        float4 av = arow_ok ? *(const float4*)Aptr : make_float4(0.f, 0.f, 0.f, 0.f);
        float4 bv = *(const float4*)Bptr;
        __syncthreads();
        As[ak + 0][ar] = av.x;
        As[ak + 1][ar] = av.y;
        As[ak + 2][ar] = av.z;
        As[ak + 3][ar] = av.w;
        *(float4*)&Bs[br][bc] = bv;
        __syncthreads();
#pragma unroll
        for (int kk = 0; kk < BKT; kk++) {
            float4 a = *(const float4*)&As[kk][ty * 4];
            float4 b = *(const float4*)&Bs[kk][tx * 4];
            acc[0][0] += a.x * b.x; acc[0][1] += a.x * b.y; acc[0][2] += a.x * b.z; acc[0][3] += a.x * b.w;
            acc[1][0] += a.y * b.x; acc[1][1] += a.y * b.y; acc[1][2] += a.y * b.z; acc[1][3] += a.y * b.w;
            acc[2][0] += a.z * b.x; acc[2][1] += a.z * b.y; acc[2][2] += a.z * b.z; acc[2][3] += a.z * b.w;
            acc[3][0] += a.w * b.x; acc[3][1] += a.w * b.y; acc[3][2] += a.w * b.z; acc[3][3] += a.w * b.w;
        }
        Aptr += BKT;
        Bptr += (long)BKT * N;
    }

    const int ncol = n0 + tx * 4;
#pragma unroll
    for (int mi = 0; mi < 4; mi++) {
        int row = m0 + ty * 4 + mi;
        if (row >= M) break;
        int orow = rowmap ? rowmap[row] : row;
        float4 o;
        float v0 = acc[mi][0] + bias[ncol + 0];
        float v1 = acc[mi][1] + bias[ncol + 1];
        float v2 = acc[mi][2] + bias[ncol + 2];
        float v3 = acc[mi][3] + bias[ncol + 3];
        if (GELU) { v0 = gelu_tanh(v0); v1 = gelu_tanh(v1); v2 = gelu_tanh(v2); v3 = gelu_tanh(v3); }
        if (RES) {
            const float4 r = *(const float4*)&C[(long)orow * N + ncol];
            v0 += r.x; v1 += r.y; v2 += r.z; v3 += r.w;
        }
        o.x = v0; o.y = v1; o.z = v2; o.w = v3;
        *(float4*)&C[(long)orow * N + ncol] = o;
    }
}

// ---------------- LayerNorm: one warp per 256-wide row ----------------
__global__ void ln_kernel(const float* __restrict__ X, const float* __restrict__ g,
                          const float* __restrict__ b, float* __restrict__ Y, int M) {
    int row = blockIdx.x * 8 + (threadIdx.x >> 5);
    int lane = threadIdx.x & 31;
    if (row >= M) return;
    const float* x = X + (long)row * DIM;
    float v[8];
    float s = 0.f;
#pragma unroll
    for (int i = 0; i < 8; i++) { v[i] = x[lane + i * 32]; s += v[i]; }
#pragma unroll
    for (int o = 16; o; o >>= 1) s += __shfl_xor_sync(0xffffffffu, s, o);
    float mean = s * (1.0f / DIM);
    float vs = 0.f;
#pragma unroll
    for (int i = 0; i < 8; i++) { float d = v[i] - mean; vs += d * d; }
#pragma unroll
    for (int o = 16; o; o >>= 1) vs += __shfl_xor_sync(0xffffffffu, vs, o);
    float inv = rsqrtf(vs * (1.0f / DIM) + 1e-5f);
    float* y = Y + (long)row * DIM;
#pragma unroll
    for (int i = 0; i < 8; i++) {
        int c = lane + i * 32;
        y[c] = (v[i] - mean) * inv * g[c] + b[c];
    }
}

// ---------------- attention: one block per bucket, 8x8 per head ----------------
#define APAD 260
__global__ void attn_kernel(const float* __restrict__ Q, const float* __restrict__ K,
                            const float* __restrict__ V, float* __restrict__ O) {
    __shared__ float Qs[8][APAD], Ks[8][APAD], Vs[8][APAD];
    const int b = blockIdx.x;
    const int t = threadIdx.x;   // 64 threads
    const long base = (long)b * (LMAX * DIM);
    for (int i = t; i < LMAX * DIM; i += 64) {
        int r = i >> 8, c = i & 255;
        Qs[r][c] = Q[base + i];
        Ks[r][c] = K[base + i];
        Vs[r][c] = V[base + i];
    }
    __syncthreads();
    const int q  = t & 7;
    const int h  = t >> 3;
    const int d0 = h * DHEAD;

    float sc[8];
    float mx = -1e30f;
#pragma unroll
    for (int k = 0; k < 8; k++) {
        float s = 0.f;
#pragma unroll
        for (int d = 0; d < DHEAD; d++) s += Qs[q][d0 + d] * Ks[k][d0 + d];
        s *= 0.17677669529663687f;   // 1/sqrt(32)
        sc[k] = s;
        mx = fmaxf(mx, s);
    }
    float sum = 0.f;
#pragma unroll
    for (int k = 0; k < 8; k++) { sc[k] = expf(sc[k] - mx); sum += sc[k]; }
    float inv = 1.0f / sum;

    float out[DHEAD];
#pragma unroll
    for (int d = 0; d < DHEAD; d++) out[d] = 0.f;
#pragma unroll
    for (int k = 0; k < 8; k++) {
        float p = sc[k] * inv;
#pragma unroll
        for (int d = 0; d < DHEAD; d++) out[d] += p * Vs[k][d0 + d];
    }
    float* op = O + base + q * DIM + d0;
#pragma unroll
    for (int d = 0; d < DHEAD; d++) op[d] = out[d];
}

// ---------------- host-side glue ----------------
static inline void launch_gemm(int mode, const float* A, const float* B, const float* bias,
                               float* C, const int* rowmap, int M, int N, int K) {
    dim3 grid(N / BN, (M + BM - 1) / BM);
    if (mode == 0)      gemm_kernel<false, false><<<grid, 256>>>(A, B, bias, C, rowmap, M, N, K);
    else if (mode == 1) gemm_kernel<true,  false><<<grid, 256>>>(A, B, bias, C, rowmap, M, N, K);
    else                gemm_kernel<false, true ><<<grid, 256>>>(A, B, bias, C, rowmap, M, N, K);
}

extern "C" void kernel_launch(void* const* d_in, const int* in_sizes, int n_in,
                              void* d_out, int out_size) {
    const float* x      = (const float*)d_in[0];
    const int*   linds  = (const int*)  d_in[1];
    const float* mlp_w  = (const float*)d_in[2];
    const float* mlp_b  = (const float*)d_in[3];
    const float* bg_tok = (const float*)d_in[4];
    const float* ln1_g  = (const float*)d_in[5];
    const float* ln1_b  = (const float*)d_in[6];
    const float* wq     = (const float*)d_in[7];
    const float* bq     = (const float*)d_in[8];
    const float* wk     = (const float*)d_in[9];
    const float* bk     = (const float*)d_in[10];
    const float* wv     = (const float*)d_in[11];
    const float* bv     = (const float*)d_in[12];
    const float* wo     = (const float*)d_in[13];
    const float* bo     = (const float*)d_in[14];
    const float* ln2_g  = (const float*)d_in[15];
    const float* ln2_b  = (const float*)d_in[16];
    const float* w1     = (const float*)d_in[17];
    const float* b1     = (const float*)d_in[18];
    const float* w2     = (const float*)d_in[19];
    const float* b2     = (const float*)d_in[20];
    const float* proj_w = (const float*)d_in[21];
    const float* proj_b = (const float*)d_in[22];
    float* out = (float*)d_out;

    float *bufA, *bufB, *ctx, *Kb, *Vb, *trx, *ff;
    int *dest, *cnt;
    cudaGetSymbolAddress((void**)&bufA, g_bufA);
    cudaGetSymbolAddress((void**)&bufB, g_bufB);
    cudaGetSymbolAddress((void**)&ctx,  g_ctx);
    cudaGetSymbolAddress((void**)&Kb,   g_K);
    cudaGetSymbolAddress((void**)&Vb,   g_V);
    cudaGetSymbolAddress((void**)&trx,  g_trx);
    cudaGetSymbolAddress((void**)&ff,   g_ff);
    cudaGetSymbolAddress((void**)&dest, g_dest);
    cudaGetSymbolAddress((void**)&cnt,  g_cnt);

    // bucket slots
    zero_cnt_kernel<<<(NB + 255) / 256, 256>>>(cnt);
    dest_kernel<<<(NOBS + 255) / 256, 256>>>(linds, cnt, dest);

    // obs MLP: gelu(gelu(x@W0+b0)@W1+b1)@W2+b2, scattered into ctx
    launch_gemm(1, x,    mlp_w + 0 * DIM * DIM, mlp_b + 0 * DIM, bufA, nullptr, NOBS, DIM, DIM);
    launch_gemm(1, bufA, mlp_w + 1 * DIM * DIM, mlp_b + 1 * DIM, bufB, nullptr, NOBS, DIM, DIM);
    launch_gemm(0, bufB, mlp_w + 2 * DIM * DIM, mlp_b + 2 * DIM, ctx,  dest,    NOBS, DIM, DIM);

    // init tr_x = broadcast bg tokens
    init_trx_kernel<<<NOBS, DIM>>>(bg_tok, trx);

    for (int l = 0; l < DEPTH; l++) {
        const long wo256 = (long)l * DIM * DIM;
        // q = LN1(tr_x) @ wq + bq
        ln_kernel<<<NOBS / 8, 256>>>(trx, ln1_g + l * DIM, ln1_b + l * DIM, bufA, NOBS);
        launch_gemm(0, bufA, wq + wo256, bq + l * DIM, bufB, nullptr, NOBS, DIM, DIM);
        // k, v from ctx
        launch_gemm(0, ctx, wk + wo256, bk + l * DIM, Kb, nullptr, NOBS, DIM, DIM);
        launch_gemm(0, ctx, wv + wo256, bv + l * DIM, Vb, nullptr, NOBS, DIM, DIM);
        // attention -> bufA
        attn_kernel<<<NB, 64>>>(bufB, Kb, Vb, bufA);
        // tr_x += O @ wo + bo
        launch_gemm(2, bufA, wo + wo256, bo + l * DIM, trx, nullptr, NOBS, DIM, DIM);
        // FFN: tr_x += gelu(LN2(tr_x)@w1+b1)@w2+b2
        ln_kernel<<<NOBS / 8, 256>>>(trx, ln2_g + l * DIM, ln2_b + l * DIM, bufA, NOBS);
        launch_gemm(1, bufA, w1 + (long)l * DIM * FF, b1 + l * FF, ff, nullptr, NOBS, FF, DIM);
        launch_gemm(2, ff, w2 + (long)l * FF * DIM, b2 + l * DIM, trx, nullptr, NOBS, DIM, FF);
    }

    // final projection: [NB, 2048] @ [2048, 512] + b  -> out
    launch_gemm(0, trx, proj_w, proj_b, out, nullptr, NB, CL, OUTD);
}

// round 2
// speedup vs baseline: 2.4787x; 2.4787x over previous
#include <cuda_runtime.h>
#include <cuda_bf16.h>
#include <cstdint>

// ---------------- problem dims ----------------
#define NOBS   72000
#define NB     9000
#define LMAX   8
#define DIM    256
#define NTOK   8
#define HEADS  8
#define DHEAD  32
#define DEPTH  8
#define FF     1024
#define OUTD   2048
#define CL     512

// ---------------- scratch (device globals; allocation-free) ----------------
__device__ float g_bufA[NOBS * DIM];
__device__ float g_bufB[NOBS * DIM];
__device__ float g_ctx [NOBS * DIM];
__device__ float g_K   [NOBS * DIM];
__device__ float g_V   [NOBS * DIM];
__device__ float g_trx [NOBS * DIM];
__device__ float g_ff  [NOBS * FF];
__device__ int   g_dest[NOBS];
__device__ int   g_cnt [NB];

// ---------------- helpers ----------------
__device__ __forceinline__ float gelu_tanh(float x) {
    const float k0 = 0.7978845608028654f;
    const float k1 = 0.044715f;
    return 0.5f * x * (1.0f + tanhf(k0 * (x + k1 * x * x * x)));
}

__device__ __forceinline__ uint32_t f2tf32(float f) {
    uint32_t u;
    asm("cvt.rna.tf32.f32 %0, %1;" : "=r"(u) : "f"(f));
    return u;
}

__device__ __forceinline__ void mma_tf32(float* d, const uint32_t* a, const uint32_t* b) {
    asm volatile(
        "mma.sync.aligned.m16n8k8.row.col.f32.tf32.tf32.f32 "
        "{%0,%1,%2,%3}, {%4,%5,%6,%7}, {%8,%9}, {%0,%1,%2,%3};"
        : "+f"(d[0]), "+f"(d[1]), "+f"(d[2]), "+f"(d[3])
        : "r"(a[0]), "r"(a[1]), "r"(a[2]), "r"(a[3]), "r"(b[0]), "r"(b[1]));
}

// ---------------- bucket slot assignment ----------------
__global__ void zero_cnt_kernel(int* cnt) {
    int i = blockIdx.x * 256 + threadIdx.x;
    if (i < NB) cnt[i] = 0;
}

__global__ void dest_kernel(const int* __restrict__ li, int* __restrict__ cnt,
                            int* __restrict__ dest) {
    int i = blockIdx.x * 256 + threadIdx.x;
    if (i >= NOBS) return;
    int f = li[3*i] * 1800 + li[3*i+1] * 60 + li[3*i+2];
    int slot = atomicAdd(&cnt[f], 1);
    dest[i] = f * LMAX + slot;
}

__global__ void init_trx_kernel(const float* __restrict__ bg, float* __restrict__ trx) {
    int tok = blockIdx.x & 7;
    trx[(long)blockIdx.x * DIM + threadIdx.x] = bg[tok * DIM + threadIdx.x];
}

// ---------------- TF32 tensor-core GEMM ----------------
// C[M,N] = epi(A[M,K] @ B[K,N] + bias); optional GELU / residual-add / row scatter.
// CTA tile 128x128x32; 8 warps as 2(M) x 4(N); warp tile 64x32.
#define TBM 128
#define TBN 128
#define TBK 32
#define ASTRIDE 36    // 128 rows x 36 (pad 4): a-frag banks = (4m+k)%32, conflict-free
#define BSTRIDE 132   // 32 rows x 132 (pad 4)

template<bool GELU, bool RES>
__global__ __launch_bounds__(256)
void gemm_tc(const float* __restrict__ A, const float* __restrict__ B,
             const float* __restrict__ bias, float* __restrict__ C,
             const int* __restrict__ rowmap, int M, int N, int K) {
    __shared__ uint32_t As[TBM * ASTRIDE];
    __shared__ uint32_t Bs[TBK * BSTRIDE];

    const int tid  = threadIdx.x;
    const int lane = tid & 31;
    const int wid  = tid >> 5;
    const int warpM = wid >> 2;       // 0..1
    const int warpN = wid & 3;        // 0..3
    const int gid  = lane >> 2;       // 0..7
    const int tig  = lane & 3;        // 0..3

    const int m0 = blockIdx.y * TBM;
    const int n0 = blockIdx.x * TBN;

    // A loader: rows ar+32i (i=0..3), cols ac..ac+3
    const int ar = tid >> 3;          // 0..31
    const int ac = (tid & 7) << 2;    // 0..28
    // B loader: rows br+8i (i=0..3), cols bc..bc+3
    const int br = tid >> 5;          // 0..7
    const int bc = (tid & 31) << 2;   // 0..124

    float acc[4][4][4];
#pragma unroll
    for (int i = 0; i < 4; i++)
#pragma unroll
        for (int j = 0; j < 4; j++)
#pragma unroll
            for (int k = 0; k < 4; k++) acc[i][j][k] = 0.0f;

    const int ntiles = K / TBK;

    float4 aReg[4], bReg[4];

    // prologue: load tile 0
#pragma unroll
    for (int i = 0; i < 4; i++) {
        int row = m0 + ar + 32 * i;
        aReg[i] = (row < M) ? *(const float4*)(A + (long)row * K + ac)
                            : make_float4(0.f, 0.f, 0.f, 0.f);
        bReg[i] = *(const float4*)(B + (long)(br + 8 * i) * N + n0 + bc);
    }

    for (int kt = 0; kt < ntiles; kt++) {
        __syncthreads();   // previous compute done reading smem
        // store current tile (convert to tf32 bits)
#pragma unroll
        for (int i = 0; i < 4; i++) {
            uint32_t* ap = &As[(ar + 32 * i) * ASTRIDE + ac];
            ap[0] = f2tf32(aReg[i].x); ap[1] = f2tf32(aReg[i].y);
            ap[2] = f2tf32(aReg[i].z); ap[3] = f2tf32(aReg[i].w);
            uint32_t* bp = &Bs[(br + 8 * i) * BSTRIDE + bc];
            bp[0] = f2tf32(bReg[i].x); bp[1] = f2tf32(bReg[i].y);
            bp[2] = f2tf32(bReg[i].z); bp[3] = f2tf32(bReg[i].w);
        }
        __syncthreads();

        // prefetch next tile into registers (overlaps with MMA below)
        if (kt + 1 < ntiles) {
            const int koff = (kt + 1) * TBK;
#pragma unroll
            for (int i = 0; i < 4; i++) {
                int row = m0 + ar + 32 * i;
                aReg[i] = (row < M) ? *(const float4*)(A + (long)row * K + koff + ac)
                                    : make_float4(0.f, 0.f, 0.f, 0.f);
                bReg[i] = *(const float4*)(B + (long)(koff + br + 8 * i) * N + n0 + bc);
            }
        }

        // compute 4 k-steps of 8
#pragma unroll
        for (int ks = 0; ks < 4; ks++) {
            const int kk = ks * 8;
            uint32_t afr[4][4], bfr[4][2];
#pragma unroll
            for (int mt = 0; mt < 4; mt++) {
                int m = warpM * 64 + mt * 16 + gid;
                afr[mt][0] = As[m * ASTRIDE + kk + tig];
                afr[mt][1] = As[(m + 8) * ASTRIDE + kk + tig];
                afr[mt][2] = As[m * ASTRIDE + kk + tig + 4];
                afr[mt][3] = As[(m + 8) * ASTRIDE + kk + tig + 4];
            }
#pragma unroll
            for (int nt = 0; nt < 4; nt++) {
                int n = warpN * 32 + nt * 8 + gid;
                bfr[nt][0] = Bs[(kk + tig) * BSTRIDE + n];
                bfr[nt][1] = Bs[(kk + tig + 4) * BSTRIDE + n];
            }
#pragma unroll
            for (int mt = 0; mt < 4; mt++)
#pragma unroll
                for (int nt = 0; nt < 4; nt++)
                    mma_tf32(acc[mt][nt], afr[mt], bfr[nt]);
        }
    }

    // epilogue
#pragma unroll
    for (int nt = 0; nt < 4; nt++) {
        const int col = n0 + warpN * 32 + nt * 8 + tig * 2;
        const float bx = bias[col], by = bias[col + 1];
#pragma unroll
        for (int mt = 0; mt < 4; mt++) {
#pragma unroll
            for (int half = 0; half < 2; half++) {
                int row = m0 + warpM * 64 + mt * 16 + gid + half * 8;
                if (row >= M) continue;
                int orow = rowmap ? rowmap[row] : row;
                float v0 = acc[mt][nt][2 * half + 0] + bx;
                float v1 = acc[mt][nt][2 * half + 1] + by;
                if (GELU) { v0 = gelu_tanh(v0); v1 = gelu_tanh(v1); }
                float* cp = C + (long)orow * N + col;
                if (RES) { v0 += cp[0]; v1 += cp[1]; }
                float2 o; o.x = v0; o.y = v1;
                *(float2*)cp = o;
            }
        }
    }
}

// ---------------- LayerNorm: one warp per 256-wide row ----------------
__global__ void ln_kernel(const float* __restrict__ X, const float* __restrict__ g,
                          const float* __restrict__ b, float* __restrict__ Y, int M) {
    int row = blockIdx.x * 8 + (threadIdx.x >> 5);
    int lane = threadIdx.x & 31;
    if (row >= M) return;
    const float* x = X + (long)row * DIM;
    float v[8];
    float s = 0.f;
#pragma unroll
    for (int i = 0; i < 8; i++) { v[i] = x[lane + i * 32]; s += v[i]; }
#pragma unroll
    for (int o = 16; o; o >>= 1) s += __shfl_xor_sync(0xffffffffu, s, o);
    float mean = s * (1.0f / DIM);
    float vs = 0.f;
#pragma unroll
    for (int i = 0; i < 8; i++) { float d = v[i] - mean; vs += d * d; }
#pragma unroll
    for (int o = 16; o; o >>= 1) vs += __shfl_xor_sync(0xffffffffu, vs, o);
    float inv = rsqrtf(vs * (1.0f / DIM) + 1e-5f);
    float* y = Y + (long)row * DIM;
#pragma unroll
    for (int i = 0; i < 8; i++) {
        int c = lane + i * 32;
        y[c] = (v[i] - mean) * inv * g[c] + b[c];
    }
}

// ---------------- attention: one block per bucket ----------------
#define APAD 260
__global__ void attn_kernel(const float* __restrict__ Q, const float* __restrict__ K,
                            const float* __restrict__ V, float* __restrict__ O) {
    __shared__ float Qs[8][APAD], Ks[8][APAD], Vs[8][APAD];
    const int b = blockIdx.x;
    const int t = threadIdx.x;
    const long base = (long)b * (LMAX * DIM);
    for (int i = t; i < LMAX * DIM; i += 64) {
        int r = i >> 8, c = i & 255;
        Qs[r][c] = Q[base + i];
        Ks[r][c] = K[base + i];
        Vs[r][c] = V[base + i];
    }
    __syncthreads();
    const int q  = t & 7;
    const int h  = t >> 3;
    const int d0 = h * DHEAD;

    float sc[8];
    float mx = -1e30f;
#pragma unroll
    for (int k = 0; k < 8; k++) {
        float s = 0.f;
#pragma unroll
        for (int d = 0; d < DHEAD; d++) s += Qs[q][d0 + d] * Ks[k][d0 + d];
        s *= 0.17677669529663687f;
        sc[k] = s;
        mx = fmaxf(mx, s);
    }
    float sum = 0.f;
#pragma unroll
    for (int k = 0; k < 8; k++) { sc[k] = expf(sc[k] - mx); sum += sc[k]; }
    float inv = 1.0f / sum;

    float out[DHEAD];
#pragma unroll
    for (int d = 0; d < DHEAD; d++) out[d] = 0.f;
#pragma unroll
    for (int k = 0; k < 8; k++) {
        float p = sc[k] * inv;
#pragma unroll
        for (int d = 0; d < DHEAD; d++) out[d] += p * Vs[k][d0 + d];
    }
    float* op = O + base + q * DIM + d0;
#pragma unroll
    for (int d = 0; d < DHEAD; d++) op[d] = out[d];
}

// ---------------- host-side glue ----------------
static inline void launch_gemm(int mode, const float* A, const float* B, const float* bias,
                               float* C, const int* rowmap, int M, int N, int K) {
    dim3 grid(N / TBN, (M + TBM - 1) / TBM);
    if (mode == 0)      gemm_tc<false, false><<<grid, 256>>>(A, B, bias, C, rowmap, M, N, K);
    else if (mode == 1) gemm_tc<true,  false><<<grid, 256>>>(A, B, bias, C, rowmap, M, N, K);
    else                gemm_tc<false, true ><<<grid, 256>>>(A, B, bias, C, rowmap, M, N, K);
}

extern "C" void kernel_launch(void* const* d_in, const int* in_sizes, int n_in,
                              void* d_out, int out_size) {
    const float* x      = (const float*)d_in[0];
    const int*   linds  = (const int*)  d_in[1];
    const float* mlp_w  = (const float*)d_in[2];
    const float* mlp_b  = (const float*)d_in[3];
    const float* bg_tok = (const float*)d_in[4];
    const float* ln1_g  = (const float*)d_in[5];
    const float* ln1_b  = (const float*)d_in[6];
    const float* wq     = (const float*)d_in[7];
    const float* bq     = (const float*)d_in[8];
    const float* wk     = (const float*)d_in[9];
    const float* bk     = (const float*)d_in[10];
    const float* wv     = (const float*)d_in[11];
    const float* bv     = (const float*)d_in[12];
    const float* wo     = (const float*)d_in[13];
    const float* bo     = (const float*)d_in[14];
    const float* ln2_g  = (const float*)d_in[15];
    const float* ln2_b  = (const float*)d_in[16];
    const float* w1     = (const float*)d_in[17];
    const float* b1     = (const float*)d_in[18];
    const float* w2     = (const float*)d_in[19];
    const float* b2     = (const float*)d_in[20];
    const float* proj_w = (const float*)d_in[21];
    const float* proj_b = (const float*)d_in[22];
    float* out = (float*)d_out;

    float *bufA, *bufB, *ctx, *Kb, *Vb, *trx, *ff;
    int *dest, *cnt;
    cudaGetSymbolAddress((void**)&bufA, g_bufA);
    cudaGetSymbolAddress((void**)&bufB, g_bufB);
    cudaGetSymbolAddress((void**)&ctx,  g_ctx);
    cudaGetSymbolAddress((void**)&Kb,   g_K);
    cudaGetSymbolAddress((void**)&Vb,   g_V);
    cudaGetSymbolAddress((void**)&trx,  g_trx);
    cudaGetSymbolAddress((void**)&ff,   g_ff);
    cudaGetSymbolAddress((void**)&dest, g_dest);
    cudaGetSymbolAddress((void**)&cnt,  g_cnt);

    zero_cnt_kernel<<<(NB + 255) / 256, 256>>>(cnt);
    dest_kernel<<<(NOBS + 255) / 256, 256>>>(linds, cnt, dest);

    // obs MLP, scattered into ctx
    launch_gemm(1, x,    mlp_w + 0 * DIM * DIM, mlp_b + 0 * DIM, bufA, nullptr, NOBS, DIM, DIM);
    launch_gemm(1, bufA, mlp_w + 1 * DIM * DIM, mlp_b + 1 * DIM, bufB, nullptr, NOBS, DIM, DIM);
    launch_gemm(0, bufB, mlp_w + 2 * DIM * DIM, mlp_b + 2 * DIM, ctx,  dest,    NOBS, DIM, DIM);

    init_trx_kernel<<<NOBS, DIM>>>(bg_tok, trx);

    for (int l = 0; l < DEPTH; l++) {
        const long wo256 = (long)l * DIM * DIM;
        ln_kernel<<<NOBS / 8, 256>>>(trx, ln1_g + l * DIM, ln1_b + l * DIM, bufA, NOBS);
        launch_gemm(0, bufA, wq + wo256, bq + l * DIM, bufB, nullptr, NOBS, DIM, DIM);
        launch_gemm(0, ctx, wk + wo256, bk + l * DIM, Kb, nullptr, NOBS, DIM, DIM);
        launch_gemm(0, ctx, wv + wo256, bv + l * DIM, Vb, nullptr, NOBS, DIM, DIM);
        attn_kernel<<<NB, 64>>>(bufB, Kb, Vb, bufA);
        launch_gemm(2, bufA, wo + wo256, bo + l * DIM, trx, nullptr, NOBS, DIM, DIM);
        ln_kernel<<<NOBS / 8, 256>>>(trx, ln2_g + l * DIM, ln2_b + l * DIM, bufA, NOBS);
        launch_gemm(1, bufA, w1 + (long)l * DIM * FF, b1 + l * FF, ff, nullptr, NOBS, FF, DIM);
        launch_gemm(2, ff, w2 + (long)l * FF * DIM, b2 + l * DIM, trx, nullptr, NOBS, DIM, FF);
    }

    launch_gemm(0, trx, proj_w, proj_b, out, nullptr, NB, CL, OUTD);
}

// round 4
// speedup vs baseline: 4.6771x; 1.8869x over previous
#include <cuda_runtime.h>
#include <cuda_fp16.h>
#include <cstdint>

// ---------------- problem dims ----------------
#define NOBS   72000
#define NB     9000
#define LMAX   8
#define DIM    256
#define HEADS  8
#define DHEAD  32
#define DEPTH  8
#define FF     1024
#define OUTD   2048
#define CL     512

// ---------------- scratch (device globals; allocation-free) ----------------
__device__ __half g_xh  [NOBS * DIM];
__device__ __half g_h1  [NOBS * DIM];
__device__ __half g_h2  [NOBS * DIM];
__device__ __half g_ctxh[NOBS * DIM];
__device__ __half g_lnh [NOBS * DIM];
__device__ __half g_Oh  [NOBS * DIM];
__device__ __half g_ffh [NOBS * FF];
__device__ __half g_trxh[NOBS * DIM];
__device__ float  g_Q   [NOBS * DIM];
__device__ float  g_K   [NOBS * DIM];
__device__ float  g_V   [NOBS * DIM];
__device__ float  g_trx [NOBS * DIM];
__device__ __half g_wTh [7536640];    // all transposed fp16 weights, 15 MB
__device__ int    g_dest[NOBS];
__device__ int    g_cnt [NB];

// transposed-weight offsets (halves)
#define OFF_MLP  0
#define OFF_WQ   196608
#define OFF_WK   720896
#define OFF_WV   1245184
#define OFF_WO   1769472
#define OFF_W1   2293760
#define OFF_W2   4390912
#define OFF_PROJ 6488064

// ---------------- helpers ----------------
__device__ __forceinline__ uint32_t smem_u32(const void* p) {
    uint32_t a;
    asm("{ .reg .u64 t; cvta.to.shared.u64 t, %1; cvt.u32.u64 %0, t; }" : "=r"(a) : "l"(p));
    return a;
}
__device__ __forceinline__ float gelu_tanh(float x) {
    const float k0 = 0.7978845608028654f, k1 = 0.044715f;
    return 0.5f * x * (1.0f + tanhf(k0 * (x + k1 * x * x * x)));
}
__device__ __forceinline__ void ldm_x4(uint32_t* r, uint32_t addr) {
    asm volatile("ldmatrix.sync.aligned.m8n8.x4.shared.b16 {%0,%1,%2,%3}, [%4];"
        : "=r"(r[0]), "=r"(r[1]), "=r"(r[2]), "=r"(r[3]) : "r"(addr));
}
__device__ __forceinline__ void mma_f16(float* d, const uint32_t* a, const uint32_t* b) {
    asm volatile("mma.sync.aligned.m16n8k16.row.col.f32.f16.f16.f32 "
        "{%0,%1,%2,%3}, {%4,%5,%6,%7}, {%8,%9}, {%0,%1,%2,%3};"
        : "+f"(d[0]), "+f"(d[1]), "+f"(d[2]), "+f"(d[3])
        : "r"(a[0]), "r"(a[1]), "r"(a[2]), "r"(a[3]), "r"(b[0]), "r"(b[1]));
}
__device__ __forceinline__ void cp16(uint32_t dst, const void* src, int srcsize) {
    asm volatile("cp.async.cg.shared.global [%0], [%1], 16, %2;"
        :: "r"(dst), "l"(src), "r"(srcsize) : "memory");
}
#define CP_COMMIT() asm volatile("cp.async.commit_group;" ::: "memory")
#define CP_WAIT1()  asm volatile("cp.async.wait_group 1;" ::: "memory")
#define SWZ(off) ((off) ^ (((off) >> 3) & 0x70))

// ---------------- setup kernels ----------------
__global__ void zero_cnt_kernel(int* cnt) {
    int i = blockIdx.x * 256 + threadIdx.x;
    if (i < NB) cnt[i] = 0;
}
__global__ void dest_kernel(const int* __restrict__ li, int* __restrict__ cnt,
                            int* __restrict__ dest) {
    int i = blockIdx.x * 256 + threadIdx.x;
    if (i >= NOBS) return;
    int f = li[3*i] * 1800 + li[3*i+1] * 60 + li[3*i+2];
    int slot = atomicAdd(&cnt[f], 1);
    dest[i] = f * LMAX + slot;
}
__global__ void init_trx_kernel(const float* __restrict__ bg, float* __restrict__ trx) {
    int tok = blockIdx.x & 7;
    trx[(long)blockIdx.x * DIM + threadIdx.x] = bg[tok * DIM + threadIdx.x];
}
__global__ void f2h_kernel(const float* __restrict__ in, __half* __restrict__ out, long n) {
    long i = ((long)blockIdx.x * 256 + threadIdx.x) * 4;
    if (i >= n) return;
    float4 v = *(const float4*)(in + i);
    __half2 a = __floats2half2_rn(v.x, v.y);
    __half2 b = __floats2half2_rn(v.z, v.w);
    *(__half2*)(out + i) = a;
    *(__half2*)(out + i + 2) = b;
}
// transpose + fp32->fp16: out[C,R] = half(in[R,C]^T), batched over z
__global__ void transpose_kernel(const float* __restrict__ in, __half* __restrict__ out,
                                 int R, int C) {
    __shared__ float tile[32][33];
    const float* src = in + (long)blockIdx.z * R * C;
    __half* dst = out + (long)blockIdx.z * R * C;
    int c0 = blockIdx.x * 32, r0 = blockIdx.y * 32;
    for (int i = threadIdx.y; i < 32; i += 8)
        tile[i][threadIdx.x] = src[(long)(r0 + i) * C + c0 + threadIdx.x];
    __syncthreads();
    for (int i = threadIdx.y; i < 32; i += 8)
        dst[(long)(c0 + i) * R + r0 + threadIdx.x] = __float2half_rn(tile[threadIdx.x][i]);
}

// ---------------- fp16 tensor-core GEMM (mma.sync + ldmatrix + cp.async) ----------------
// C[M,N] = epi(A[M,K] @ Bt[N,K]^T + bias)
// CTA tile 128x128, K-chunk 64 halves, 3-stage cp.async pipeline.
// 8 warps: warpM = wid>>2 (0..1), warpN = wid&3 (0..3); warp tile 64x32.
#define BM 128
#define BN 128
#define BKH 64
#define STG_BYTES 32768   // 16KB A + 16KB B per stage
#define GSMEM (3 * STG_BYTES)

template<bool GELU, bool RES, bool F32O, bool HO>
__global__ __launch_bounds__(256)
void gemm_h(const __half* __restrict__ A, const __half* __restrict__ Bt,
            const float* __restrict__ bias, float* __restrict__ C,
            __half* __restrict__ Ch, const int* __restrict__ rowmap,
            int M, int N, int K) {
    extern __shared__ char smem[];
    const uint32_t sb = smem_u32(smem);
    const int tid = threadIdx.x;
    const int lane = tid & 31, wid = tid >> 5;
    const int warpM = wid >> 2, warpN = wid & 3;
    const int m0 = blockIdx.y * BM, n0 = blockIdx.x * BN;
    const int ntiles = K / BKH;

    float acc[4][4][4];
#pragma unroll
    for (int i = 0; i < 4; i++)
#pragma unroll
        for (int j = 0; j < 4; j++)
#pragma unroll
            for (int k = 0; k < 4; k++) acc[i][j][k] = 0.0f;

    // async loader: 1024 16B-chunks per operand tile; 4 per thread each
    auto issue = [&](int stage, int kt) {
        const int kb = kt * BKH;
        const uint32_t abase = sb + stage * STG_BYTES;
        const uint32_t bbase = abase + 16384;
#pragma unroll
        for (int i = 0; i < 4; i++) {
            int chunk = tid + 256 * i;
            int row = chunk >> 3, cc = chunk & 7;
            int gr = m0 + row;
            const __half* src = A + (long)(gr < M ? gr : 0) * K + kb + cc * 8;
            cp16(abase + SWZ(row * 128 + cc * 16), src, gr < M ? 16 : 0);
        }
#pragma unroll
        for (int i = 0; i < 4; i++) {
            int chunk = tid + 256 * i;
            int row = chunk >> 3, cc = chunk & 7;
            const __half* src = Bt + (long)(n0 + row) * K + kb + cc * 8;
            cp16(bbase + SWZ(row * 128 + cc * 16), src, 16);
        }
    };

    issue(0, 0); CP_COMMIT();
    issue(1, 1); CP_COMMIT();

    const int lm = lane >> 3, lr = lane & 7;   // ldmatrix: matrix idx, row-in-matrix

    for (int kt = 0; kt < ntiles; kt++) {
        CP_WAIT1();
        __syncthreads();
        const int stage = kt % 3;
        const uint32_t abase = sb + stage * STG_BYTES;
        const uint32_t bbase = abase + 16384;
#pragma unroll
        for (int ks = 0; ks < 4; ks++) {
            const int k0 = ks * 16;
            uint32_t afr[4][4], bfr[2][4];
#pragma unroll
            for (int mt = 0; mt < 4; mt++) {
                int row = warpM * 64 + mt * 16 + (lm & 1) * 8 + lr;
                int colh = k0 + (lm >> 1) * 8;
                ldm_x4(afr[mt], abase + SWZ(row * 128 + colh * 2));
            }
#pragma unroll
            for (int nt = 0; nt < 2; nt++) {
                int row = warpN * 32 + nt * 16 + (lm & 1) * 8 + lr;
                int colh = k0 + (lm >> 1) * 8;
                ldm_x4(bfr[nt], bbase + SWZ(row * 128 + colh * 2));
            }
#pragma unroll
            for (int mt = 0; mt < 4; mt++)
#pragma unroll
                for (int j = 0; j < 4; j++) {
                    uint32_t b2[2] = { bfr[j >> 1][j & 1], bfr[j >> 1][(j & 1) + 2] };
                    mma_f16(acc[mt][j], afr[mt], b2);
                }
        }
        if (kt + 2 < ntiles) issue((kt + 2) % 3, kt + 2);
        CP_COMMIT();
        __syncthreads();
    }

    // epilogue: d0,d1 -> (row g, col 2t); d2,d3 -> (row g+8)
    const int g = lane >> 2, t = lane & 3;
#pragma unroll
    for (int j = 0; j < 4; j++) {
        const int col = n0 + warpN * 32 + j * 8 + t * 2;
        const float bx = __ldg(&bias[col]), by = __ldg(&bias[col + 1]);
#pragma unroll
        for (int mt = 0; mt < 4; mt++) {
#pragma unroll
            for (int h = 0; h < 2; h++) {
                int row = m0 + warpM * 64 + mt * 16 + g + h * 8;
                if (row >= M) continue;
                int orow = rowmap ? rowmap[row] : row;
                float v0 = acc[mt][j][2 * h + 0] + bx;
                float v1 = acc[mt][j][2 * h + 1] + by;
                if (GELU) { v0 = gelu_tanh(v0); v1 = gelu_tanh(v1); }
                if (RES) {
                    float2 r = *(const float2*)(C + (long)orow * N + col);
                    v0 += r.x; v1 += r.y;
                }
                if (F32O) {
                    float2 o; o.x = v0; o.y = v1;
                    *(float2*)(C + (long)orow * N + col) = o;
                }
                if (HO) *(__half2*)(Ch + (long)orow * N + col) = __floats2half2_rn(v0, v1);
            }
        }
    }
}

// ---------------- LayerNorm: fp32 in, fp16 out ----------------
__global__ void ln_kernel(const float* __restrict__ X, const float* __restrict__ g,
                          const float* __restrict__ b, __half* __restrict__ Y, int M) {
    int row = blockIdx.x * 8 + (threadIdx.x >> 5);
    int lane = threadIdx.x & 31;
    if (row >= M) return;
    const float* x = X + (long)row * DIM;
    float v[8], s = 0.f;
#pragma unroll
    for (int i = 0; i < 8; i++) { v[i] = x[lane + i * 32]; s += v[i]; }
#pragma unroll
    for (int o = 16; o; o >>= 1) s += __shfl_xor_sync(0xffffffffu, s, o);
    float mean = s * (1.0f / DIM), vs = 0.f;
#pragma unroll
    for (int i = 0; i < 8; i++) { float d = v[i] - mean; vs += d * d; }
#pragma unroll
    for (int o = 16; o; o >>= 1) vs += __shfl_xor_sync(0xffffffffu, vs, o);
    float inv = rsqrtf(vs * (1.0f / DIM) + 1e-5f);
    __half* y = Y + (long)row * DIM;
#pragma unroll
    for (int i = 0; i < 8; i++) {
        int c = lane + i * 32;
        y[c] = __float2half_rn((v[i] - mean) * inv * g[c] + b[c]);
    }
}

// ---------------- attention: fp32 Q,K,V in, fp16 O out ----------------
#define APAD 260
__global__ void attn_kernel(const float* __restrict__ Q, const float* __restrict__ K,
                            const float* __restrict__ V, __half* __restrict__ O) {
    __shared__ float Qs[8][APAD], Ks[8][APAD], Vs[8][APAD];
    const int b = blockIdx.x;
    const int t = threadIdx.x;
    const long base = (long)b * (LMAX * DIM);
    for (int i = t; i < LMAX * DIM; i += 64) {
        int r = i >> 8, c = i & 255;
        Qs[r][c] = Q[base + i]; Ks[r][c] = K[base + i]; Vs[r][c] = V[base + i];
    }
    __syncthreads();
    const int q = t & 7, h = t >> 3, d0 = h * DHEAD;
    float sc[8], mx = -1e30f;
#pragma unroll
    for (int k = 0; k < 8; k++) {
        float s = 0.f;
#pragma unroll
        for (int d = 0; d < DHEAD; d++) s += Qs[q][d0 + d] * Ks[k][d0 + d];
        s *= 0.17677669529663687f;
        sc[k] = s; mx = fmaxf(mx, s);
    }
    float sum = 0.f;
#pragma unroll
    for (int k = 0; k < 8; k++) { sc[k] = expf(sc[k] - mx); sum += sc[k]; }
    float inv = 1.0f / sum;
    float out[DHEAD];
#pragma unroll
    for (int d = 0; d < DHEAD; d++) out[d] = 0.f;
#pragma unroll
    for (int k = 0; k < 8; k++) {
        float p = sc[k] * inv;
#pragma unroll
        for (int d = 0; d < DHEAD; d++) out[d] += p * Vs[k][d0 + d];
    }
    __half* op = O + base + q * DIM + d0;
#pragma unroll
    for (int d = 0; d < DHEAD; d++) op[d] = __float2half_rn(out[d]);
}

// ---------------- host glue ----------------
// modes: 0 = fp32-out | 1 = gelu, half-out | 2 = residual, fp32-out
//        3 = half-out (scatter)            | 4 = residual, fp32-out + half-out
static inline void launch_gemm(int mode, const __half* A, const __half* Bt, const float* bias,
                               float* C, __half* Ch, const int* rowmap, int M, int N, int K) {
    dim3 grid(N / BN, (M + BM - 1) / BM);
    switch (mode) {
    case 0: gemm_h<false, false, true,  false><<<grid, 256, GSMEM>>>(A, Bt, bias, C, Ch, rowmap, M, N, K); break;
    case 1: gemm_h<true,  false, false, true ><<<grid, 256, GSMEM>>>(A, Bt, bias, C, Ch, rowmap, M, N, K); break;
    case 2: gemm_h<false, true,  true,  false><<<grid, 256, GSMEM>>>(A, Bt, bias, C, Ch, rowmap, M, N, K); break;
    case 3: gemm_h<false, false, false, true ><<<grid, 256, GSMEM>>>(A, Bt, bias, C, Ch, rowmap, M, N, K); break;
    case 4: gemm_h<false, true,  true,  true ><<<grid, 256, GSMEM>>>(A, Bt, bias, C, Ch, rowmap, M, N, K); break;
    }
}

extern "C" void kernel_launch(void* const* d_in, const int* in_sizes, int n_in,
                              void* d_out, int out_size) {
    const float* x      = (const float*)d_in[0];
    const int*   linds  = (const int*)  d_in[1];
    const float* mlp_w  = (const float*)d_in[2];
    const float* mlp_b  = (const float*)d_in[3];
    const float* bg_tok = (const float*)d_in[4];
    const float* ln1_g  = (const float*)d_in[5];
    const float* ln1_b  = (const float*)d_in[6];
    const float* wq     = (const float*)d_in[7];
    const float* bq     = (const float*)d_in[8];
    const float* wk     = (const float*)d_in[9];
    const float* bk     = (const float*)d_in[10];
    const float* wv     = (const float*)d_in[11];
    const float* bv     = (const float*)d_in[12];
    const float* wo     = (const float*)d_in[13];
    const float* bo     = (const float*)d_in[14];
    const float* ln2_g  = (const float*)d_in[15];
    const float* ln2_b  = (const float*)d_in[16];
    const float* w1     = (const float*)d_in[17];
    const float* b1     = (const float*)d_in[18];
    const float* w2     = (const float*)d_in[19];
    const float* b2     = (const float*)d_in[20];
    const float* proj_w = (const float*)d_in[21];
    const float* proj_b = (const float*)d_in[22];
    float* out = (float*)d_out;

    __half *xh, *h1, *h2, *ctxh, *lnh, *Oh, *ffh, *trxh, *wTh;
    float *Qb, *Kb, *Vb, *trx;
    int *dest, *cnt;
    cudaGetSymbolAddress((void**)&xh,   g_xh);
    cudaGetSymbolAddress((void**)&h1,   g_h1);
    cudaGetSymbolAddress((void**)&h2,   g_h2);
    cudaGetSymbolAddress((void**)&ctxh, g_ctxh);
    cudaGetSymbolAddress((void**)&lnh,  g_lnh);
    cudaGetSymbolAddress((void**)&Oh,   g_Oh);
    cudaGetSymbolAddress((void**)&ffh,  g_ffh);
    cudaGetSymbolAddress((void**)&trxh, g_trxh);
    cudaGetSymbolAddress((void**)&Qb,   g_Q);
    cudaGetSymbolAddress((void**)&Kb,   g_K);
    cudaGetSymbolAddress((void**)&Vb,   g_V);
    cudaGetSymbolAddress((void**)&trx,  g_trx);
    cudaGetSymbolAddress((void**)&wTh,  g_wTh);
    cudaGetSymbolAddress((void**)&dest, g_dest);
    cudaGetSymbolAddress((void**)&cnt,  g_cnt);

    cudaFuncSetAttribute(gemm_h<false, false, true,  false>, cudaFuncAttributeMaxDynamicSharedMemorySize, GSMEM);
    cudaFuncSetAttribute(gemm_h<true,  false, false, true >, cudaFuncAttributeMaxDynamicSharedMemorySize, GSMEM);
    cudaFuncSetAttribute(gemm_h<false, true,  true,  false>, cudaFuncAttributeMaxDynamicSharedMemorySize, GSMEM);
    cudaFuncSetAttribute(gemm_h<false, false, false, true >, cudaFuncAttributeMaxDynamicSharedMemorySize, GSMEM);
    cudaFuncSetAttribute(gemm_h<false, true,  true,  true >, cudaFuncAttributeMaxDynamicSharedMemorySize, GSMEM);

    // weight transposes + fp16 convert: [K,N] -> half [N,K]
    dim3 tb(32, 8);
    transpose_kernel<<<dim3(8,  8, 3), tb>>>(mlp_w,  wTh + OFF_MLP, 256, 256);
    transpose_kernel<<<dim3(8,  8, 8), tb>>>(wq,     wTh + OFF_WQ,  256, 256);
    transpose_kernel<<<dim3(8,  8, 8), tb>>>(wk,     wTh + OFF_WK,  256, 256);
    transpose_kernel<<<dim3(8,  8, 8), tb>>>(wv,     wTh + OFF_WV,  256, 256);
    transpose_kernel<<<dim3(8,  8, 8), tb>>>(wo,     wTh + OFF_WO,  256, 256);
    transpose_kernel<<<dim3(32, 8, 8), tb>>>(w1,     wTh + OFF_W1,  256, 1024);
    transpose_kernel<<<dim3(8, 32, 8), tb>>>(w2,     wTh + OFF_W2,  1024, 256);
    transpose_kernel<<<dim3(16, 64, 1), tb>>>(proj_w, wTh + OFF_PROJ, 2048, 512);

    zero_cnt_kernel<<<(NB + 255) / 256, 256>>>(cnt);
    dest_kernel<<<(NOBS + 255) / 256, 256>>>(linds, cnt, dest);
    f2h_kernel<<<(NOBS * DIM / 4 + 255) / 256, 256>>>(x, xh, (long)NOBS * DIM);

    // obs MLP (fp16 in, fp16 out), final layer scattered into ctxh
    launch_gemm(1, xh, wTh + OFF_MLP + 0 * DIM * DIM, mlp_b + 0 * DIM, nullptr, h1,   nullptr, NOBS, DIM, DIM);
    launch_gemm(1, h1, wTh + OFF_MLP + 1 * DIM * DIM, mlp_b + 1 * DIM, nullptr, h2,   nullptr, NOBS, DIM, DIM);
    launch_gemm(3, h2, wTh + OFF_MLP + 2 * DIM * DIM, mlp_b + 2 * DIM, nullptr, ctxh, dest,    NOBS, DIM, DIM);

    init_trx_kernel<<<NOBS, DIM>>>(bg_tok, trx);

    for (int l = 0; l < DEPTH; l++) {
        const long o256 = (long)l * DIM * DIM;
        ln_kernel<<<NOBS / 8, 256>>>(trx, ln1_g + l * DIM, ln1_b + l * DIM, lnh, NOBS);
        launch_gemm(0, lnh,  wTh + OFF_WQ + o256, bq + l * DIM, Qb, nullptr, nullptr, NOBS, DIM, DIM);
        launch_gemm(0, ctxh, wTh + OFF_WK + o256, bk + l * DIM, Kb, nullptr, nullptr, NOBS, DIM, DIM);
        launch_gemm(0, ctxh, wTh + OFF_WV + o256, bv + l * DIM, Vb, nullptr, nullptr, NOBS, DIM, DIM);
        attn_kernel<<<NB, 64>>>(Qb, Kb, Vb, Oh);
        launch_gemm(2, Oh, wTh + OFF_WO + o256, bo + l * DIM, trx, nullptr, nullptr, NOBS, DIM, DIM);
        ln_kernel<<<NOBS / 8, 256>>>(trx, ln2_g + l * DIM, ln2_b + l * DIM, lnh, NOBS);
        launch_gemm(1, lnh, wTh + OFF_W1 + (long)l * DIM * FF, b1 + l * FF, nullptr, ffh, nullptr, NOBS, FF, DIM);
        if (l < DEPTH - 1)
            launch_gemm(2, ffh, wTh + OFF_W2 + (long)l * DIM * FF, b2 + l * DIM, trx, nullptr, nullptr, NOBS, DIM, FF);
        else
            launch_gemm(4, ffh, wTh + OFF_W2 + (long)l * DIM * FF, b2 + l * DIM, trx, trxh, nullptr, NOBS, DIM, FF);
    }

    // final projection: [NB, 2048] @ [2048, 512]^T-free -> out
    launch_gemm(0, trxh, wTh + OFF_PROJ, proj_b, out, nullptr, nullptr, NB, CL, OUTD);
}